// round 1
// baseline (speedup 1.0000x reference)
#include <cuda_runtime.h>
#include <cuda_bf16.h>
#include <math.h>

// Problem constants
#define N_NODES 50000
#define N_EDGES 800000
#define NODE_F  128
#define EDGE_F  32
#define TIME_D  16
#define MEM_D   128
#define MSG_D   128

// Scratch (device globals — no allocation allowed)
__device__ float g_XA[N_NODES * MSG_D];    // x@W1_x + b1 per node
__device__ float g_H[N_NODES * MSG_D];     // sum of h1 per target node
__device__ float g_CNT[N_NODES];           // in-degree (float)
__device__ float g_AGG[N_NODES * MEM_D];   // mean(messages)
__device__ float g_GI[N_NODES * 3 * MEM_D];
__device__ float g_MEM[N_NODES * MEM_D];

__device__ __forceinline__ void red_add_v4(float* addr, float a, float b, float c, float d) {
    asm volatile("red.global.add.v4.f32 [%0], {%1,%2,%3,%4};"
                 :: "l"(addr), "f"(a), "f"(b), "f"(c), "f"(d) : "memory");
}

__device__ __forceinline__ float sigmoidf_(float x) {
    return 1.0f / (1.0f + expf(-x));
}

// ---------------------------------------------------------------------------
// Zero scratch
// ---------------------------------------------------------------------------
__global__ void zero_kernel(float* __restrict__ H, float* __restrict__ C) {
    int idx = blockIdx.x * blockDim.x + threadIdx.x;
    const int nH = N_NODES * MSG_D;
    if (idx < nH) H[idx] = 0.0f;
    if (idx < N_NODES) C[idx] = 0.0f;
}

// ---------------------------------------------------------------------------
// Generic fp32 tiled GEMM: C[M,N] = A[M,K] @ B (+bias), optional row mean+mask
// TRANSB: B element (k,n) read from B[n*K + k] (i.e., C = A @ B^T)
// If cnt != nullptr: C[m,:] = (cnt[m] > 0) ? acc/cnt[m] + bias : 0
// ---------------------------------------------------------------------------
template<bool TRANSB>
__global__ void gemm_kernel(const float* __restrict__ A, const float* __restrict__ B,
                            const float* __restrict__ bias, const float* __restrict__ cnt,
                            float* __restrict__ C, int M, int N, int K)
{
    constexpr int BM = 64, BN = 64, BK = 16;
    __shared__ float As[BM][BK + 1];
    __shared__ float Bs[BK][BN];

    const int m0 = blockIdx.x * BM;
    const int n0 = blockIdx.y * BN;
    const int tid = threadIdx.x;     // 128 threads
    const int ty = tid >> 4;         // 0..7  -> 8 rows each
    const int tx = tid & 15;         // 0..15 -> 4 cols each

    float acc[8][4];
    #pragma unroll
    for (int i = 0; i < 8; i++)
        #pragma unroll
        for (int j = 0; j < 4; j++) acc[i][j] = 0.0f;

    for (int k0 = 0; k0 < K; k0 += BK) {
        #pragma unroll
        for (int i = 0; i < 8; i++) {
            int idx = i * 128 + tid;          // 0..1023
            int m = idx >> 4, kk = idx & 15;
            int gm = m0 + m;
            float v = 0.0f;
            if (gm < M) v = A[(size_t)gm * K + k0 + kk];
            As[m][kk] = v;
        }
        #pragma unroll
        for (int i = 0; i < 8; i++) {
            int idx = i * 128 + tid;
            if (TRANSB) {
                int nn = idx >> 4, kk = idx & 15;
                Bs[kk][nn] = B[(size_t)(n0 + nn) * K + k0 + kk];
            } else {
                int kk = idx >> 6, nn = idx & 63;
                Bs[kk][nn] = B[(size_t)(k0 + kk) * N + n0 + nn];
            }
        }
        __syncthreads();
        #pragma unroll
        for (int kk = 0; kk < BK; kk++) {
            float4 b4 = *(const float4*)&Bs[kk][tx * 4];
            float a[8];
            #pragma unroll
            for (int i = 0; i < 8; i++) a[i] = As[ty * 8 + i][kk];
            #pragma unroll
            for (int i = 0; i < 8; i++) {
                acc[i][0] = fmaf(a[i], b4.x, acc[i][0]);
                acc[i][1] = fmaf(a[i], b4.y, acc[i][1]);
                acc[i][2] = fmaf(a[i], b4.z, acc[i][2]);
                acc[i][3] = fmaf(a[i], b4.w, acc[i][3]);
            }
        }
        __syncthreads();
    }

    const int gn = n0 + tx * 4;
    float4 bi = *(const float4*)&bias[gn];
    #pragma unroll
    for (int i = 0; i < 8; i++) {
        int gm = m0 + ty * 8 + i;
        if (gm >= M) continue;
        float4 o;
        if (cnt != nullptr) {
            float c = cnt[gm];
            if (c > 0.0f) {
                float inv = 1.0f / c;
                o.x = acc[i][0] * inv + bi.x;
                o.y = acc[i][1] * inv + bi.y;
                o.z = acc[i][2] * inv + bi.z;
                o.w = acc[i][3] * inv + bi.w;
            } else {
                o.x = o.y = o.z = o.w = 0.0f;
            }
        } else {
            o.x = acc[i][0] + bi.x;
            o.y = acc[i][1] + bi.y;
            o.z = acc[i][2] + bi.z;
            o.w = acc[i][3] + bi.w;
        }
        *(float4*)&C[(size_t)gm * N + gn] = o;
    }
}

// ---------------------------------------------------------------------------
// Edge kernel: per edge, col j:
//   h1[j] = relu( XA[src][j] + sum_k ea[k]*W1e[k][j] + sum_k te[k]*W1t[k][j] )
// scatter-add h1 into H[tgt], count into CNT[tgt].
// Weights (48 x 1 col) live in registers; 128 threads = 128 cols; 8 edges/iter.
// ---------------------------------------------------------------------------
__global__ void edge_kernel(const float* __restrict__ XA,
                            const float* __restrict__ edge_attr,
                            const float* __restrict__ t,
                            const float* __restrict__ time_w,
                            const float* __restrict__ time_b,
                            const float* __restrict__ msg_w1,
                            const int* __restrict__ edge_index,
                            float* __restrict__ H, float* __restrict__ CNT)
{
    constexpr int U = 8;
    __shared__ float ea_s[U][EDGE_F];
    __shared__ float te_s[U][TIME_D];
    __shared__ int   src_s[U];
    __shared__ int   tgt_s[U];
    __shared__ float tw_s[TIME_D], tb_s[TIME_D];

    const int tid = threadIdx.x;   // 128 threads, tid = output column j
    if (tid < TIME_D) { tw_s[tid] = time_w[tid]; tb_s[tid] = time_b[tid]; }

    // Per-column weights in registers: W1 rows 128..159 (edge), 160..175 (time)
    float we[EDGE_F], wt[TIME_D];
    #pragma unroll
    for (int k = 0; k < EDGE_F; k++) we[k] = msg_w1[(size_t)(NODE_F + k) * MSG_D + tid];
    #pragma unroll
    for (int k = 0; k < TIME_D; k++) wt[k] = msg_w1[(size_t)(NODE_F + EDGE_F + k) * MSG_D + tid];
    __syncthreads();

    const int ngroups = N_EDGES / U;   // 100000 exactly
    for (int g = blockIdx.x; g < ngroups; g += gridDim.x) {
        const int e0 = g * U;
        // cooperative load of 8 edges' attrs (256 floats, coalesced)
        #pragma unroll
        for (int i = 0; i < 2; i++) {
            int idx = i * 128 + tid;
            int e = idx >> 5, k = idx & 31;
            ea_s[e][k] = edge_attr[(size_t)(e0 + e) * EDGE_F + k];
        }
        if (tid < U)            src_s[tid]     = edge_index[e0 + tid];
        else if (tid < 2 * U)   tgt_s[tid - U] = edge_index[N_EDGES + e0 + (tid - U)];
        {
            int e = tid >> 4, k = tid & 15;
            te_s[e][k] = cosf(t[e0 + e] * tw_s[k] + tb_s[k]);
        }
        __syncthreads();

        #pragma unroll
        for (int u = 0; u < U; u++) {
            const int s  = src_s[u];
            const int gt = tgt_s[u];
            float acc = XA[(size_t)s * MSG_D + tid];   // includes b1
            const float4* ea4 = (const float4*)ea_s[u];
            #pragma unroll
            for (int k4 = 0; k4 < EDGE_F / 4; k4++) {
                float4 v = ea4[k4];
                acc = fmaf(v.x, we[k4 * 4 + 0], acc);
                acc = fmaf(v.y, we[k4 * 4 + 1], acc);
                acc = fmaf(v.z, we[k4 * 4 + 2], acc);
                acc = fmaf(v.w, we[k4 * 4 + 3], acc);
            }
            const float4* te4 = (const float4*)te_s[u];
            #pragma unroll
            for (int k4 = 0; k4 < TIME_D / 4; k4++) {
                float4 v = te4[k4];
                acc = fmaf(v.x, wt[k4 * 4 + 0], acc);
                acc = fmaf(v.y, wt[k4 * 4 + 1], acc);
                acc = fmaf(v.z, wt[k4 * 4 + 2], acc);
                acc = fmaf(v.w, wt[k4 * 4 + 3], acc);
            }
            float h  = fmaxf(acc, 0.0f);
            float h1 = __shfl_down_sync(0xffffffffu, h, 1);
            float h2 = __shfl_down_sync(0xffffffffu, h, 2);
            float h3 = __shfl_down_sync(0xffffffffu, h, 3);
            if ((tid & 3) == 0)
                red_add_v4(&H[(size_t)gt * MSG_D + tid], h, h1, h2, h3);
            if (tid == 0)
                atomicAdd(&CNT[gt], 1.0f);
        }
        __syncthreads();
    }
}

// ---------------------------------------------------------------------------
// GRU elementwise (h0 = 0 -> gh = b_hh):
//   r = sig(gi_r + bhh_r); z = sig(gi_z + bhh_z); n = tanh(gi_n + r*bhh_n)
//   memory = (1-z)*n
// ---------------------------------------------------------------------------
__global__ void gru_kernel(const float* __restrict__ GI, const float* __restrict__ b_hh,
                           float* __restrict__ MEM)
{
    int idx = blockIdx.x * blockDim.x + threadIdx.x;
    const int n = N_NODES * MEM_D;
    if (idx >= n) return;
    int m = idx >> 7, j = idx & 127;
    const float* gi = GI + (size_t)m * (3 * MEM_D);
    float r  = sigmoidf_(gi[j]             + b_hh[j]);
    float z  = sigmoidf_(gi[MEM_D + j]     + b_hh[MEM_D + j]);
    float nn = tanhf    (gi[2 * MEM_D + j] + r * b_hh[2 * MEM_D + j]);
    MEM[idx] = (1.0f - z) * nn;
}

// ---------------------------------------------------------------------------
extern "C" void kernel_launch(void* const* d_in, const int* in_sizes, int n_in,
                              void* d_out, int out_size)
{
    const float* x         = (const float*)d_in[0];
    const float* edge_attr = (const float*)d_in[1];
    const float* t         = (const float*)d_in[2];
    const float* time_w    = (const float*)d_in[3];
    const float* time_b    = (const float*)d_in[4];
    const float* msg_w1    = (const float*)d_in[5];
    const float* msg_b1    = (const float*)d_in[6];
    const float* msg_w2    = (const float*)d_in[7];
    const float* msg_b2    = (const float*)d_in[8];
    const float* gru_w_ih  = (const float*)d_in[9];
    // d_in[10] = gru_w_hh: unused (h0 == 0)
    const float* gru_b_ih  = (const float*)d_in[11];
    const float* gru_b_hh  = (const float*)d_in[12];
    const float* out_w     = (const float*)d_in[13];
    const float* out_b     = (const float*)d_in[14];
    const int*   edge_idx  = (const int*)d_in[15];
    float* out = (float*)d_out;

    float *XA, *H, *CNT, *AGG, *GI, *MEM;
    cudaGetSymbolAddress((void**)&XA,  g_XA);
    cudaGetSymbolAddress((void**)&H,   g_H);
    cudaGetSymbolAddress((void**)&CNT, g_CNT);
    cudaGetSymbolAddress((void**)&AGG, g_AGG);
    cudaGetSymbolAddress((void**)&GI,  g_GI);
    cudaGetSymbolAddress((void**)&MEM, g_MEM);

    const int M = N_NODES;
    const int mtiles = (M + 63) / 64;   // 782

    // 1) zero H, CNT
    zero_kernel<<<(N_NODES * MSG_D + 255) / 256, 256>>>(H, CNT);

    // 2) XA = x @ W1_x + b1   (per node)
    {
        dim3 grid(mtiles, MSG_D / 64);
        gemm_kernel<false><<<grid, 128>>>(x, msg_w1, msg_b1, nullptr, XA, M, MSG_D, NODE_F);
    }

    // 3) edge stage: h1 + scatter-add
    edge_kernel<<<2048, 128>>>(XA, edge_attr, t, time_w, time_b, msg_w1, edge_idx, H, CNT);

    // 4) AGG = (H/cnt) @ W2 + b2   (masked to 0 where cnt == 0)
    {
        dim3 grid(mtiles, MEM_D / 64);
        gemm_kernel<false><<<grid, 128>>>(H, msg_w2, msg_b2, CNT, AGG, M, MEM_D, MSG_D);
    }

    // 5) GI = AGG @ W_ih^T + b_ih
    {
        dim3 grid(mtiles, (3 * MEM_D) / 64);
        gemm_kernel<true><<<grid, 128>>>(AGG, gru_w_ih, gru_b_ih, nullptr, GI, M, 3 * MEM_D, MEM_D);
    }

    // 6) GRU elementwise -> MEM
    gru_kernel<<<(N_NODES * MEM_D + 255) / 256, 256>>>(GI, gru_b_hh, MEM);

    // 7) out = MEM @ out_w^T + out_b
    {
        dim3 grid(mtiles, NODE_F / 64);
        gemm_kernel<true><<<grid, 128>>>(MEM, out_w, out_b, nullptr, out, M, NODE_F, MEM_D);
    }
}

// round 6
// speedup vs baseline: 1.2329x; 1.2329x over previous
#include <cuda_runtime.h>
#include <math.h>
#include <stdint.h>

#define N_NODES 50000
#define N_EDGES 800000
#define NODE_F  128
#define EDGE_F  32
#define TIME_D  16
#define MEM_D   128
#define MSG_D   128

// Scratch (device globals — no allocation allowed)
__device__ float g_XA[N_NODES * MSG_D];    // x@W1_x + b1 per node
__device__ float g_H[N_NODES * MSG_D];     // sum of h1 per target node
__device__ float g_CNT[N_NODES];           // in-degree
__device__ float g_AGG[N_NODES * MEM_D];
__device__ float g_GI[N_NODES * 3 * MEM_D];
__device__ float g_MEM[N_NODES * MEM_D];

__device__ __forceinline__ uint32_t f2tf(float f) {
    uint32_t r; asm("cvt.rna.tf32.f32 %0, %1;" : "=r"(r) : "f"(f)); return r;
}

__device__ __forceinline__ void mma8(float* c, uint32_t a0, uint32_t a1, uint32_t a2,
                                     uint32_t a3, uint32_t b0, uint32_t b1) {
    asm volatile(
        "mma.sync.aligned.m16n8k8.row.col.f32.tf32.tf32.f32 "
        "{%0,%1,%2,%3}, {%4,%5,%6,%7}, {%8,%9}, {%0,%1,%2,%3};"
        : "+f"(c[0]), "+f"(c[1]), "+f"(c[2]), "+f"(c[3])
        : "r"(a0), "r"(a1), "r"(a2), "r"(a3), "r"(b0), "r"(b1));
}

__device__ __forceinline__ void red_add_v4(float* addr, float a, float b, float c, float d) {
    asm volatile("red.global.add.v4.f32 [%0], {%1,%2,%3,%4};"
                 :: "l"(addr), "f"(a), "f"(b), "f"(c), "f"(d) : "memory");
}

__device__ __forceinline__ float sigmoidf_(float x) { return 1.0f / (1.0f + expf(-x)); }

// ---------------------------------------------------------------------------
__global__ void zero_kernel(float* __restrict__ H, float* __restrict__ C) {
    int idx = blockIdx.x * blockDim.x + threadIdx.x;
    if (idx < N_NODES * MSG_D) H[idx] = 0.0f;
    if (idx < N_NODES) C[idx] = 0.0f;
}

// ---------------------------------------------------------------------------
// tf32 tensor-core GEMM: C[M,N] = A[M,128] @ B (+bias)
// TRANSB: B element (k,n) from B[n*128+k].  MEANMASK: /cnt[m], 0 if cnt==0.
// Block: 128 threads (4 warps), tile 64x64, K=128 in two 64-wide stages.
// ---------------------------------------------------------------------------
template<bool TRANSB, bool MEANMASK>
__global__ void __launch_bounds__(128) gemm_tf32(
    const float* __restrict__ A, const float* __restrict__ B,
    const float* __restrict__ bias, const float* __restrict__ cnt,
    float* __restrict__ C, int M, int N)
{
    __shared__ uint32_t As[64][68];
    __shared__ uint32_t Bs[64][73];
    const int tid = threadIdx.x;
    const int lane = tid & 31, w = tid >> 5;
    const int lr = lane >> 2, lc = lane & 3;
    const int m0 = blockIdx.x * 64, n0 = blockIdx.y * 64;

    float c[8][4];
    #pragma unroll
    for (int i = 0; i < 8; i++) { c[i][0] = c[i][1] = c[i][2] = c[i][3] = 0.f; }

    for (int ks = 0; ks < 128; ks += 64) {
        #pragma unroll
        for (int i = 0; i < 8; i++) {
            int idx = i * 128 + tid;
            int m = idx >> 4, k4 = idx & 15;
            int gm = m0 + m;
            float4 v = make_float4(0.f, 0.f, 0.f, 0.f);
            if (gm < M) v = *(const float4*)&A[(size_t)gm * 128 + ks + k4 * 4];
            As[m][k4*4+0] = f2tf(v.x); As[m][k4*4+1] = f2tf(v.y);
            As[m][k4*4+2] = f2tf(v.z); As[m][k4*4+3] = f2tf(v.w);
        }
        #pragma unroll
        for (int i = 0; i < 8; i++) {
            int idx = i * 128 + tid;
            if (TRANSB) {
                int n = idx >> 4, k4 = idx & 15;
                float4 v = *(const float4*)&B[(size_t)(n0 + n) * 128 + ks + k4 * 4];
                Bs[k4*4+0][n] = f2tf(v.x); Bs[k4*4+1][n] = f2tf(v.y);
                Bs[k4*4+2][n] = f2tf(v.z); Bs[k4*4+3][n] = f2tf(v.w);
            } else {
                int k = idx >> 4, n4 = idx & 15;
                float4 v = *(const float4*)&B[(size_t)(ks + k) * N + n0 + n4 * 4];
                Bs[k][n4*4+0] = f2tf(v.x); Bs[k][n4*4+1] = f2tf(v.y);
                Bs[k][n4*4+2] = f2tf(v.z); Bs[k][n4*4+3] = f2tf(v.w);
            }
        }
        __syncthreads();
        #pragma unroll
        for (int kk = 0; kk < 8; kk++) {
            uint32_t a0 = As[w*16+lr  ][kk*8+lc  ];
            uint32_t a1 = As[w*16+lr+8][kk*8+lc  ];
            uint32_t a2 = As[w*16+lr  ][kk*8+lc+4];
            uint32_t a3 = As[w*16+lr+8][kk*8+lc+4];
            #pragma unroll
            for (int nt = 0; nt < 8; nt++) {
                uint32_t b0 = Bs[kk*8+lc  ][nt*8+lr];
                uint32_t b1 = Bs[kk*8+lc+4][nt*8+lr];
                mma8(c[nt], a0, a1, a2, a3, b0, b1);
            }
        }
        __syncthreads();
    }

    const int gm0 = m0 + w * 16 + lr, gm1 = gm0 + 8;
    float s0 = 1.f, s1 = 1.f; bool z0 = false, z1 = false;
    if (MEANMASK) {
        if (gm0 < M) { float cc = cnt[gm0]; if (cc > 0.f) s0 = 1.f / cc; else z0 = true; }
        if (gm1 < M) { float cc = cnt[gm1]; if (cc > 0.f) s1 = 1.f / cc; else z1 = true; }
    }
    #pragma unroll
    for (int nt = 0; nt < 8; nt++) {
        int n = n0 + nt * 8 + lc * 2;
        float bx = bias[n], by = bias[n + 1];
        if (gm0 < M) {
            float2 o;
            if (MEANMASK) {
                if (z0) { o.x = 0.f; o.y = 0.f; }
                else    { o.x = c[nt][0] * s0 + bx; o.y = c[nt][1] * s0 + by; }
            } else      { o.x = c[nt][0] + bx;      o.y = c[nt][1] + by; }
            *(float2*)&C[(size_t)gm0 * N + n] = o;
        }
        if (gm1 < M) {
            float2 o;
            if (MEANMASK) {
                if (z1) { o.x = 0.f; o.y = 0.f; }
                else    { o.x = c[nt][2] * s1 + bx; o.y = c[nt][3] * s1 + by; }
            } else      { o.x = c[nt][2] + bx;      o.y = c[nt][3] + by; }
            *(float2*)&C[(size_t)gm1 * N + n] = o;
        }
    }
}

// ---------------------------------------------------------------------------
// Edge kernel (R1 proven FFMA version): per edge, col j:
//   h1[j] = relu( XA[src][j] + sum_k ea[k]*W1e[k][j] + sum_k te[k]*W1t[k][j] )
// scatter-add h1 into H[tgt], count into CNT[tgt].
// ---------------------------------------------------------------------------
__global__ void edge_kernel(const float* __restrict__ XA,
                            const float* __restrict__ edge_attr,
                            const float* __restrict__ t,
                            const float* __restrict__ time_w,
                            const float* __restrict__ time_b,
                            const float* __restrict__ msg_w1,
                            const int* __restrict__ edge_index,
                            float* __restrict__ H, float* __restrict__ CNT)
{
    constexpr int U = 8;
    __shared__ float ea_s[U][EDGE_F];
    __shared__ float te_s[U][TIME_D];
    __shared__ int   src_s[U];
    __shared__ int   tgt_s[U];
    __shared__ float tw_s[TIME_D], tb_s[TIME_D];

    const int tid = threadIdx.x;   // 128 threads, tid = output column j
    if (tid < TIME_D) { tw_s[tid] = time_w[tid]; tb_s[tid] = time_b[tid]; }

    // Per-column weights in registers: W1 rows 128..159 (edge), 160..175 (time)
    float we[EDGE_F], wt[TIME_D];
    #pragma unroll
    for (int k = 0; k < EDGE_F; k++) we[k] = msg_w1[(size_t)(NODE_F + k) * MSG_D + tid];
    #pragma unroll
    for (int k = 0; k < TIME_D; k++) wt[k] = msg_w1[(size_t)(NODE_F + EDGE_F + k) * MSG_D + tid];
    __syncthreads();

    const int ngroups = N_EDGES / U;   // 100000 exactly
    for (int g = blockIdx.x; g < ngroups; g += gridDim.x) {
        const int e0 = g * U;
        #pragma unroll
        for (int i = 0; i < 2; i++) {
            int idx = i * 128 + tid;
            int e = idx >> 5, k = idx & 31;
            ea_s[e][k] = edge_attr[(size_t)(e0 + e) * EDGE_F + k];
        }
        if (tid < U)            src_s[tid]     = edge_index[e0 + tid];
        else if (tid < 2 * U)   tgt_s[tid - U] = edge_index[N_EDGES + e0 + (tid - U)];
        {
            int e = tid >> 4, k = tid & 15;
            te_s[e][k] = cosf(t[e0 + e] * tw_s[k] + tb_s[k]);
        }
        __syncthreads();

        #pragma unroll
        for (int u = 0; u < U; u++) {
            const int s  = src_s[u];
            const int gt = tgt_s[u];
            float acc = XA[(size_t)s * MSG_D + tid];   // includes b1
            const float4* ea4 = (const float4*)ea_s[u];
            #pragma unroll
            for (int k4 = 0; k4 < EDGE_F / 4; k4++) {
                float4 v = ea4[k4];
                acc = fmaf(v.x, we[k4 * 4 + 0], acc);
                acc = fmaf(v.y, we[k4 * 4 + 1], acc);
                acc = fmaf(v.z, we[k4 * 4 + 2], acc);
                acc = fmaf(v.w, we[k4 * 4 + 3], acc);
            }
            const float4* te4 = (const float4*)te_s[u];
            #pragma unroll
            for (int k4 = 0; k4 < TIME_D / 4; k4++) {
                float4 v = te4[k4];
                acc = fmaf(v.x, wt[k4 * 4 + 0], acc);
                acc = fmaf(v.y, wt[k4 * 4 + 1], acc);
                acc = fmaf(v.z, wt[k4 * 4 + 2], acc);
                acc = fmaf(v.w, wt[k4 * 4 + 3], acc);
            }
            float h  = fmaxf(acc, 0.0f);
            float h1 = __shfl_down_sync(0xffffffffu, h, 1);
            float h2 = __shfl_down_sync(0xffffffffu, h, 2);
            float h3 = __shfl_down_sync(0xffffffffu, h, 3);
            if ((tid & 3) == 0)
                red_add_v4(&H[(size_t)gt * MSG_D + tid], h, h1, h2, h3);
            if (tid == 0)
                atomicAdd(&CNT[gt], 1.0f);
        }
        __syncthreads();
    }
}

// ---------------------------------------------------------------------------
__global__ void gru_kernel(const float* __restrict__ GI, const float* __restrict__ b_hh,
                           float* __restrict__ MEM)
{
    int idx = blockIdx.x * blockDim.x + threadIdx.x;
    if (idx >= N_NODES * MEM_D) return;
    int m = idx >> 7, j = idx & 127;
    const float* gi = GI + (size_t)m * (3 * MEM_D);
    float r  = sigmoidf_(gi[j]             + b_hh[j]);
    float z  = sigmoidf_(gi[MEM_D + j]     + b_hh[MEM_D + j]);
    float nn = tanhf    (gi[2 * MEM_D + j] + r * b_hh[2 * MEM_D + j]);
    MEM[idx] = (1.0f - z) * nn;
}

// ---------------------------------------------------------------------------
extern "C" void kernel_launch(void* const* d_in, const int* in_sizes, int n_in,
                              void* d_out, int out_size)
{
    const float* x         = (const float*)d_in[0];
    const float* edge_attr = (const float*)d_in[1];
    const float* t         = (const float*)d_in[2];
    const float* time_w    = (const float*)d_in[3];
    const float* time_b    = (const float*)d_in[4];
    const float* msg_w1    = (const float*)d_in[5];
    const float* msg_b1    = (const float*)d_in[6];
    const float* msg_w2    = (const float*)d_in[7];
    const float* msg_b2    = (const float*)d_in[8];
    const float* gru_w_ih  = (const float*)d_in[9];
    // d_in[10] = gru_w_hh: unused (h0 == 0)
    const float* gru_b_ih  = (const float*)d_in[11];
    const float* gru_b_hh  = (const float*)d_in[12];
    const float* out_w     = (const float*)d_in[13];
    const float* out_b     = (const float*)d_in[14];
    const int*   edge_idx  = (const int*)d_in[15];
    float* out = (float*)d_out;

    float *XA, *H, *CNT, *AGG, *GI, *MEM;
    cudaGetSymbolAddress((void**)&XA,  g_XA);
    cudaGetSymbolAddress((void**)&H,   g_H);
    cudaGetSymbolAddress((void**)&CNT, g_CNT);
    cudaGetSymbolAddress((void**)&AGG, g_AGG);
    cudaGetSymbolAddress((void**)&GI,  g_GI);
    cudaGetSymbolAddress((void**)&MEM, g_MEM);

    const int M = N_NODES;
    const int mtiles = (M + 63) / 64;   // 782

    // 1) zero H, CNT
    zero_kernel<<<(N_NODES * MSG_D + 255) / 256, 256>>>(H, CNT);

    // 2) XA = x @ W1_x + b1   (tf32 mma)
    gemm_tf32<false, false><<<dim3(mtiles, 2), 128>>>(x, msg_w1, msg_b1, nullptr, XA, M, MSG_D);

    // 3) edge stage (proven FFMA kernel)
    edge_kernel<<<2048, 128>>>(XA, edge_attr, t, time_w, time_b, msg_w1, edge_idx, H, CNT);

    // 4) AGG = mean(H) @ W2 + b2  (masked to 0 where cnt==0)
    gemm_tf32<false, true><<<dim3(mtiles, 2), 128>>>(H, msg_w2, msg_b2, CNT, AGG, M, MEM_D);

    // 5) GI = AGG @ W_ih^T + b_ih
    gemm_tf32<true, false><<<dim3(mtiles, 6), 128>>>(AGG, gru_w_ih, gru_b_ih, nullptr, GI, M, 3 * MEM_D);

    // 6) GRU elementwise
    gru_kernel<<<(N_NODES * MEM_D + 255) / 256, 256>>>(GI, gru_b_hh, MEM);

    // 7) out = MEM @ out_w^T + out_b
    gemm_tf32<true, false><<<dim3(mtiles, 2), 128>>>(MEM, out_w, out_b, nullptr, out, M, NODE_F);
}

// round 8
// speedup vs baseline: 1.4122x; 1.1454x over previous
#include <cuda_runtime.h>
#include <math.h>
#include <stdint.h>

#define N_NODES 50000
#define N_EDGES 800000
#define NODE_F  128
#define EDGE_F  32
#define TIME_D  16
#define MEM_D   128
#define MSG_D   128

// Scratch (device globals — no allocation allowed)
__device__ float g_XA[N_NODES * MSG_D];    // x@W1_x + b1 per node
__device__ float g_H[N_NODES * MSG_D];     // sum of h1 per target node
__device__ float g_CNT[N_NODES];           // in-degree
__device__ float g_AGG[N_NODES * MEM_D];
__device__ float g_GI[N_NODES * 3 * MEM_D];
__device__ float g_MEM[N_NODES * MEM_D];

__device__ __forceinline__ uint32_t f2tf(float f) {
    uint32_t r; asm("cvt.rna.tf32.f32 %0, %1;" : "=r"(r) : "f"(f)); return r;
}

__device__ __forceinline__ void mma8(float* c, uint32_t a0, uint32_t a1, uint32_t a2,
                                     uint32_t a3, uint32_t b0, uint32_t b1) {
    asm volatile(
        "mma.sync.aligned.m16n8k8.row.col.f32.tf32.tf32.f32 "
        "{%0,%1,%2,%3}, {%4,%5,%6,%7}, {%8,%9}, {%0,%1,%2,%3};"
        : "+f"(c[0]), "+f"(c[1]), "+f"(c[2]), "+f"(c[3])
        : "r"(a0), "r"(a1), "r"(a2), "r"(a3), "r"(b0), "r"(b1));
}

__device__ __forceinline__ void red_add_v4(float* addr, float a, float b, float c, float d) {
    asm volatile("red.global.add.v4.f32 [%0], {%1,%2,%3,%4};"
                 :: "l"(addr), "f"(a), "f"(b), "f"(c), "f"(d) : "memory");
}

__device__ __forceinline__ float sigmoidf_(float x) { return 1.0f / (1.0f + expf(-x)); }

// ---------------------------------------------------------------------------
__global__ void zero_kernel(float* __restrict__ H, float* __restrict__ C) {
    int idx = blockIdx.x * blockDim.x + threadIdx.x;
    if (idx < N_NODES * MSG_D) H[idx] = 0.0f;
    if (idx < N_NODES) C[idx] = 0.0f;
}

// ---------------------------------------------------------------------------
// tf32 tensor-core GEMM: C[M,N] = A[M,128] @ B (+bias)  (proven in R6)
// ---------------------------------------------------------------------------
template<bool TRANSB, bool MEANMASK>
__global__ void __launch_bounds__(128) gemm_tf32(
    const float* __restrict__ A, const float* __restrict__ B,
    const float* __restrict__ bias, const float* __restrict__ cnt,
    float* __restrict__ C, int M, int N)
{
    __shared__ uint32_t As[64][68];
    __shared__ uint32_t Bs[64][73];
    const int tid = threadIdx.x;
    const int lane = tid & 31, w = tid >> 5;
    const int lr = lane >> 2, lc = lane & 3;
    const int m0 = blockIdx.x * 64, n0 = blockIdx.y * 64;

    float c[8][4];
    #pragma unroll
    for (int i = 0; i < 8; i++) { c[i][0] = c[i][1] = c[i][2] = c[i][3] = 0.f; }

    for (int ks = 0; ks < 128; ks += 64) {
        #pragma unroll
        for (int i = 0; i < 8; i++) {
            int idx = i * 128 + tid;
            int m = idx >> 4, k4 = idx & 15;
            int gm = m0 + m;
            float4 v = make_float4(0.f, 0.f, 0.f, 0.f);
            if (gm < M) v = *(const float4*)&A[(size_t)gm * 128 + ks + k4 * 4];
            As[m][k4*4+0] = f2tf(v.x); As[m][k4*4+1] = f2tf(v.y);
            As[m][k4*4+2] = f2tf(v.z); As[m][k4*4+3] = f2tf(v.w);
        }
        #pragma unroll
        for (int i = 0; i < 8; i++) {
            int idx = i * 128 + tid;
            if (TRANSB) {
                int n = idx >> 4, k4 = idx & 15;
                float4 v = *(const float4*)&B[(size_t)(n0 + n) * 128 + ks + k4 * 4];
                Bs[k4*4+0][n] = f2tf(v.x); Bs[k4*4+1][n] = f2tf(v.y);
                Bs[k4*4+2][n] = f2tf(v.z); Bs[k4*4+3][n] = f2tf(v.w);
            } else {
                int k = idx >> 4, n4 = idx & 15;
                float4 v = *(const float4*)&B[(size_t)(ks + k) * N + n0 + n4 * 4];
                Bs[k][n4*4+0] = f2tf(v.x); Bs[k][n4*4+1] = f2tf(v.y);
                Bs[k][n4*4+2] = f2tf(v.z); Bs[k][n4*4+3] = f2tf(v.w);
            }
        }
        __syncthreads();
        #pragma unroll
        for (int kk = 0; kk < 8; kk++) {
            uint32_t a0 = As[w*16+lr  ][kk*8+lc  ];
            uint32_t a1 = As[w*16+lr+8][kk*8+lc  ];
            uint32_t a2 = As[w*16+lr  ][kk*8+lc+4];
            uint32_t a3 = As[w*16+lr+8][kk*8+lc+4];
            #pragma unroll
            for (int nt = 0; nt < 8; nt++) {
                uint32_t b0 = Bs[kk*8+lc  ][nt*8+lr];
                uint32_t b1 = Bs[kk*8+lc+4][nt*8+lr];
                mma8(c[nt], a0, a1, a2, a3, b0, b1);
            }
        }
        __syncthreads();
    }

    const int gm0 = m0 + w * 16 + lr, gm1 = gm0 + 8;
    float s0 = 1.f, s1 = 1.f; bool z0 = false, z1 = false;
    if (MEANMASK) {
        if (gm0 < M) { float cc = cnt[gm0]; if (cc > 0.f) s0 = 1.f / cc; else z0 = true; }
        if (gm1 < M) { float cc = cnt[gm1]; if (cc > 0.f) s1 = 1.f / cc; else z1 = true; }
    }
    #pragma unroll
    for (int nt = 0; nt < 8; nt++) {
        int n = n0 + nt * 8 + lc * 2;
        float bx = bias[n], by = bias[n + 1];
        if (gm0 < M) {
            float2 o;
            if (MEANMASK) {
                if (z0) { o.x = 0.f; o.y = 0.f; }
                else    { o.x = c[nt][0] * s0 + bx; o.y = c[nt][1] * s0 + by; }
            } else      { o.x = c[nt][0] + bx;      o.y = c[nt][1] + by; }
            *(float2*)&C[(size_t)gm0 * N + n] = o;
        }
        if (gm1 < M) {
            float2 o;
            if (MEANMASK) {
                if (z1) { o.x = 0.f; o.y = 0.f; }
                else    { o.x = c[nt][2] * s1 + bx; o.y = c[nt][3] * s1 + by; }
            } else      { o.x = c[nt][2] + bx;      o.y = c[nt][3] + by; }
            *(float2*)&C[(size_t)gm1 * N + n] = o;
        }
    }
}

// ---------------------------------------------------------------------------
// Edge kernel v2 (tensor-core + proven scatter):
//   Phase 1: EW[64,128] = [ea|te][64,48] @ W1_et[48,128]  (tf32 mma)
//   Phase 2: stage EW to shared (EVEN row stride 130 -> float2-safe), then
//            the R1-proven epilogue: thread=column, loop edges, +XA[src],
//            relu, shfl-pack, red.add.v4 into H[tgt].
// ---------------------------------------------------------------------------
__global__ void __launch_bounds__(128) edge_mma2(
    const float* __restrict__ edge_attr, const float* __restrict__ t,
    const float* __restrict__ time_w, const float* __restrict__ time_b,
    const float* __restrict__ msg_w1, const int* __restrict__ edge_index,
    const float* __restrict__ XA, float* __restrict__ H, float* __restrict__ CNT)
{
    // Raw shared buffer: phase1 = Ae[64][53] u32 (13568B) + Bw[48][129] u32 (24768B)
    //                    phase2 = Cs[64][130] floats (33280B) — reused, stride EVEN
    __shared__ __align__(16) char sm_raw[13568 + 24768];
    uint32_t (*Ae)[53]  = reinterpret_cast<uint32_t(*)[53]>(sm_raw);
    uint32_t (*Bw)[129] = reinterpret_cast<uint32_t(*)[129]>(sm_raw + 13568);
    float    (*Cs)[130] = reinterpret_cast<float(*)[130]>(sm_raw);
    __shared__ int src_s[64], tgt_s[64];
    __shared__ float tw_s[TIME_D], tb_s[TIME_D];

    const int tid = threadIdx.x;
    const int lane = tid & 31, w = tid >> 5;
    const int lr = lane >> 2, lc = lane & 3;
    const int e0 = blockIdx.x * 64;

    if (tid < TIME_D) { tw_s[tid] = time_w[tid]; tb_s[tid] = time_b[tid]; }
    if (tid >= 64) {
        int i = tid - 64;
        int tg = edge_index[N_EDGES + e0 + i];
        tgt_s[i] = tg;
        atomicAdd(&CNT[tg], 1.0f);
    } else {
        src_s[tid] = edge_index[e0 + tid];
    }
    // W1_et -> Bw  (48 rows x 128 cols)
    #pragma unroll
    for (int i = 0; i < 12; i++) {
        int idx = i * 128 + tid;          // 0..1535 float4s
        int k = idx >> 5, n4 = idx & 31;
        float4 v = *(const float4*)&msg_w1[(size_t)(NODE_F + k) * MSG_D + n4 * 4];
        Bw[k][n4*4+0] = f2tf(v.x); Bw[k][n4*4+1] = f2tf(v.y);
        Bw[k][n4*4+2] = f2tf(v.z); Bw[k][n4*4+3] = f2tf(v.w);
    }
    // edge_attr -> Ae[:, 0:32]
    #pragma unroll
    for (int i = 0; i < 4; i++) {
        int idx = i * 128 + tid;          // 0..511 float4s
        int e = idx >> 3, k4 = idx & 7;
        float4 v = *(const float4*)&edge_attr[(size_t)(e0 + e) * EDGE_F + k4 * 4];
        Ae[e][k4*4+0] = f2tf(v.x); Ae[e][k4*4+1] = f2tf(v.y);
        Ae[e][k4*4+2] = f2tf(v.z); Ae[e][k4*4+3] = f2tf(v.w);
    }
    __syncthreads();
    // time enc -> Ae[:, 32:48]
    #pragma unroll
    for (int i = 0; i < 8; i++) {
        int idx = i * 128 + tid;          // 0..1023
        int e = idx >> 4, k = idx & 15;
        Ae[e][EDGE_F + k] = f2tf(cosf(t[e0 + e] * tw_s[k] + tb_s[k]));
    }
    __syncthreads();

    // A fragments into registers (frees Ae for reuse after the next sync)
    uint32_t a[6][4];
    #pragma unroll
    for (int kk = 0; kk < 6; kk++) {
        a[kk][0] = Ae[w*16+lr  ][kk*8+lc  ];
        a[kk][1] = Ae[w*16+lr+8][kk*8+lc  ];
        a[kk][2] = Ae[w*16+lr  ][kk*8+lc+4];
        a[kk][3] = Ae[w*16+lr+8][kk*8+lc+4];
    }

    float c[16][4];
    #pragma unroll
    for (int i = 0; i < 16; i++) { c[i][0] = c[i][1] = c[i][2] = c[i][3] = 0.f; }

    #pragma unroll
    for (int kk = 0; kk < 6; kk++) {
        #pragma unroll
        for (int nt = 0; nt < 16; nt++) {
            uint32_t b0 = Bw[kk*8+lc  ][nt*8+lr];
            uint32_t b1 = Bw[kk*8+lc+4][nt*8+lr];
            mma8(c[nt], a[kk][0], a[kk][1], a[kk][2], a[kk][3], b0, b1);
        }
    }
    __syncthreads();   // all reads of Ae/Bw complete — safe to overwrite with Cs

    // Stage accumulators to shared. Row stride 130 (even) -> float2 stores are
    // 8B-aligned for every edge row (this was the R7 misaligned-address bug).
    const int er0 = w * 16 + lr, er1 = er0 + 8;
    #pragma unroll
    for (int nt = 0; nt < 16; nt++) {
        const int n = nt * 8 + lc * 2;
        *(float2*)&Cs[er0][n] = make_float2(c[nt][0], c[nt][1]);
        *(float2*)&Cs[er1][n] = make_float2(c[nt][2], c[nt][3]);
    }
    __syncthreads();

    // R1-proven epilogue: thread tid = output column
    for (int e = 0; e < 64; e++) {
        const int s  = src_s[e];
        const int gt = tgt_s[e];
        float h = fmaxf(Cs[e][tid] + XA[(size_t)s * MSG_D + tid], 0.0f);
        float h1 = __shfl_down_sync(0xffffffffu, h, 1);
        float h2 = __shfl_down_sync(0xffffffffu, h, 2);
        float h3 = __shfl_down_sync(0xffffffffu, h, 3);
        if ((tid & 3) == 0)
            red_add_v4(&H[(size_t)gt * MSG_D + tid], h, h1, h2, h3);
    }
}

// ---------------------------------------------------------------------------
__global__ void gru_kernel(const float* __restrict__ GI, const float* __restrict__ b_hh,
                           float* __restrict__ MEM)
{
    int idx = blockIdx.x * blockDim.x + threadIdx.x;
    if (idx >= N_NODES * MEM_D) return;
    int m = idx >> 7, j = idx & 127;
    const float* gi = GI + (size_t)m * (3 * MEM_D);
    float r  = sigmoidf_(gi[j]             + b_hh[j]);
    float z  = sigmoidf_(gi[MEM_D + j]     + b_hh[MEM_D + j]);
    float nn = tanhf    (gi[2 * MEM_D + j] + r * b_hh[2 * MEM_D + j]);
    MEM[idx] = (1.0f - z) * nn;
}

// ---------------------------------------------------------------------------
extern "C" void kernel_launch(void* const* d_in, const int* in_sizes, int n_in,
                              void* d_out, int out_size)
{
    const float* x         = (const float*)d_in[0];
    const float* edge_attr = (const float*)d_in[1];
    const float* t         = (const float*)d_in[2];
    const float* time_w    = (const float*)d_in[3];
    const float* time_b    = (const float*)d_in[4];
    const float* msg_w1    = (const float*)d_in[5];
    const float* msg_b1    = (const float*)d_in[6];
    const float* msg_w2    = (const float*)d_in[7];
    const float* msg_b2    = (const float*)d_in[8];
    const float* gru_w_ih  = (const float*)d_in[9];
    // d_in[10] = gru_w_hh: unused (h0 == 0)
    const float* gru_b_ih  = (const float*)d_in[11];
    const float* gru_b_hh  = (const float*)d_in[12];
    const float* out_w     = (const float*)d_in[13];
    const float* out_b     = (const float*)d_in[14];
    const int*   edge_idx  = (const int*)d_in[15];
    float* out = (float*)d_out;

    float *XA, *H, *CNT, *AGG, *GI, *MEM;
    cudaGetSymbolAddress((void**)&XA,  g_XA);
    cudaGetSymbolAddress((void**)&H,   g_H);
    cudaGetSymbolAddress((void**)&CNT, g_CNT);
    cudaGetSymbolAddress((void**)&AGG, g_AGG);
    cudaGetSymbolAddress((void**)&GI,  g_GI);
    cudaGetSymbolAddress((void**)&MEM, g_MEM);

    const int M = N_NODES;
    const int mtiles = (M + 63) / 64;   // 782

    // 1) zero H, CNT
    zero_kernel<<<(N_NODES * MSG_D + 255) / 256, 256>>>(H, CNT);

    // 2) XA = x @ W1_x + b1
    gemm_tf32<false, false><<<dim3(mtiles, 2), 128>>>(x, msg_w1, msg_b1, nullptr, XA, M, MSG_D);

    // 3) edge stage (tensor-core MLP + proven scatter epilogue)
    edge_mma2<<<N_EDGES / 64, 128>>>(edge_attr, t, time_w, time_b, msg_w1, edge_idx, XA, H, CNT);

    // 4) AGG = mean(H) @ W2 + b2  (masked to 0 where cnt==0)
    gemm_tf32<false, true><<<dim3(mtiles, 2), 128>>>(H, msg_w2, msg_b2, CNT, AGG, M, MEM_D);

    // 5) GI = AGG @ W_ih^T + b_ih
    gemm_tf32<true, false><<<dim3(mtiles, 6), 128>>>(AGG, gru_w_ih, gru_b_ih, nullptr, GI, M, 3 * MEM_D);

    // 6) GRU elementwise
    gru_kernel<<<(N_NODES * MEM_D + 255) / 256, 256>>>(GI, gru_b_hh, MEM);

    // 7) out = MEM @ out_w^T + out_b
    gemm_tf32<true, false><<<dim3(mtiles, 2), 128>>>(MEM, out_w, out_b, nullptr, out, M, NODE_F);
}

// round 10
// speedup vs baseline: 1.7295x; 1.2247x over previous
#include <cuda_runtime.h>
#include <math.h>
#include <stdint.h>

#define N_NODES 50000
#define N_EDGES 800000
#define NODE_F  128
#define EDGE_F  32
#define TIME_D  16
#define MEM_D   128
#define MSG_D   128

// Scratch (device globals — no allocation allowed)
__device__ float g_XA[N_NODES * MSG_D];    // x@W1_x + b1 per node
__device__ float g_H[N_NODES * MSG_D];     // sum of h1 per target node
__device__ float g_CNT[N_NODES];           // in-degree
__device__ float g_AGG[N_NODES * MEM_D];
__device__ float g_GI[N_NODES * 3 * MEM_D];
__device__ float g_MEM[N_NODES * MEM_D];

__device__ __forceinline__ uint32_t f2tf(float f) {
    uint32_t r; asm("cvt.rna.tf32.f32 %0, %1;" : "=r"(r) : "f"(f)); return r;
}

__device__ __forceinline__ void mma8(float* c, uint32_t a0, uint32_t a1, uint32_t a2,
                                     uint32_t a3, uint32_t b0, uint32_t b1) {
    asm volatile(
        "mma.sync.aligned.m16n8k8.row.col.f32.tf32.tf32.f32 "
        "{%0,%1,%2,%3}, {%4,%5,%6,%7}, {%8,%9}, {%0,%1,%2,%3};"
        : "+f"(c[0]), "+f"(c[1]), "+f"(c[2]), "+f"(c[3])
        : "r"(a0), "r"(a1), "r"(a2), "r"(a3), "r"(b0), "r"(b1));
}

__device__ __forceinline__ void red_add_v4(float* addr, float a, float b, float c, float d) {
    asm volatile("red.global.add.v4.f32 [%0], {%1,%2,%3,%4};"
                 :: "l"(addr), "f"(a), "f"(b), "f"(c), "f"(d) : "memory");
}

__device__ __forceinline__ float sigmoidf_(float x) { return 1.0f / (1.0f + expf(-x)); }

// ---------------------------------------------------------------------------
__global__ void zero_kernel(float* __restrict__ H, float* __restrict__ C) {
    int idx = blockIdx.x * blockDim.x + threadIdx.x;
    if (idx < N_NODES * MSG_D) H[idx] = 0.0f;
    if (idx < N_NODES) C[idx] = 0.0f;
}

// ---------------------------------------------------------------------------
// tf32 tensor-core GEMM: C[M,N] = A[M,128] @ B (+bias)  (proven in R6/R8)
// ---------------------------------------------------------------------------
template<bool TRANSB, bool MEANMASK>
__global__ void __launch_bounds__(128) gemm_tf32(
    const float* __restrict__ A, const float* __restrict__ B,
    const float* __restrict__ bias, const float* __restrict__ cnt,
    float* __restrict__ C, int M, int N)
{
    __shared__ uint32_t As[64][68];
    __shared__ uint32_t Bs[64][73];
    const int tid = threadIdx.x;
    const int lane = tid & 31, w = tid >> 5;
    const int lr = lane >> 2, lc = lane & 3;
    const int m0 = blockIdx.x * 64, n0 = blockIdx.y * 64;

    float c[8][4];
    #pragma unroll
    for (int i = 0; i < 8; i++) { c[i][0] = c[i][1] = c[i][2] = c[i][3] = 0.f; }

    for (int ks = 0; ks < 128; ks += 64) {
        #pragma unroll
        for (int i = 0; i < 8; i++) {
            int idx = i * 128 + tid;
            int m = idx >> 4, k4 = idx & 15;
            int gm = m0 + m;
            float4 v = make_float4(0.f, 0.f, 0.f, 0.f);
            if (gm < M) v = *(const float4*)&A[(size_t)gm * 128 + ks + k4 * 4];
            As[m][k4*4+0] = f2tf(v.x); As[m][k4*4+1] = f2tf(v.y);
            As[m][k4*4+2] = f2tf(v.z); As[m][k4*4+3] = f2tf(v.w);
        }
        #pragma unroll
        for (int i = 0; i < 8; i++) {
            int idx = i * 128 + tid;
            if (TRANSB) {
                int n = idx >> 4, k4 = idx & 15;
                float4 v = *(const float4*)&B[(size_t)(n0 + n) * 128 + ks + k4 * 4];
                Bs[k4*4+0][n] = f2tf(v.x); Bs[k4*4+1][n] = f2tf(v.y);
                Bs[k4*4+2][n] = f2tf(v.z); Bs[k4*4+3][n] = f2tf(v.w);
            } else {
                int k = idx >> 4, n4 = idx & 15;
                float4 v = *(const float4*)&B[(size_t)(ks + k) * N + n0 + n4 * 4];
                Bs[k][n4*4+0] = f2tf(v.x); Bs[k][n4*4+1] = f2tf(v.y);
                Bs[k][n4*4+2] = f2tf(v.z); Bs[k][n4*4+3] = f2tf(v.w);
            }
        }
        __syncthreads();
        #pragma unroll
        for (int kk = 0; kk < 8; kk++) {
            uint32_t a0 = As[w*16+lr  ][kk*8+lc  ];
            uint32_t a1 = As[w*16+lr+8][kk*8+lc  ];
            uint32_t a2 = As[w*16+lr  ][kk*8+lc+4];
            uint32_t a3 = As[w*16+lr+8][kk*8+lc+4];
            #pragma unroll
            for (int nt = 0; nt < 8; nt++) {
                uint32_t b0 = Bs[kk*8+lc  ][nt*8+lr];
                uint32_t b1 = Bs[kk*8+lc+4][nt*8+lr];
                mma8(c[nt], a0, a1, a2, a3, b0, b1);
            }
        }
        __syncthreads();
    }

    const int gm0 = m0 + w * 16 + lr, gm1 = gm0 + 8;
    float s0 = 1.f, s1 = 1.f; bool z0 = false, z1 = false;
    if (MEANMASK) {
        if (gm0 < M) { float cc = cnt[gm0]; if (cc > 0.f) s0 = 1.f / cc; else z0 = true; }
        if (gm1 < M) { float cc = cnt[gm1]; if (cc > 0.f) s1 = 1.f / cc; else z1 = true; }
    }
    #pragma unroll
    for (int nt = 0; nt < 8; nt++) {
        int n = n0 + nt * 8 + lc * 2;
        float bx = bias[n], by = bias[n + 1];
        if (gm0 < M) {
            float2 o;
            if (MEANMASK) {
                if (z0) { o.x = 0.f; o.y = 0.f; }
                else    { o.x = c[nt][0] * s0 + bx; o.y = c[nt][1] * s0 + by; }
            } else      { o.x = c[nt][0] + bx;      o.y = c[nt][1] + by; }
            *(float2*)&C[(size_t)gm0 * N + n] = o;
        }
        if (gm1 < M) {
            float2 o;
            if (MEANMASK) {
                if (z1) { o.x = 0.f; o.y = 0.f; }
                else    { o.x = c[nt][2] * s1 + bx; o.y = c[nt][3] * s1 + by; }
            } else      { o.x = c[nt][2] + bx;      o.y = c[nt][3] + by; }
            *(float2*)&C[(size_t)gm1 * N + n] = o;
        }
    }
}

// ---------------------------------------------------------------------------
// Edge kernel v3 (tensor-core + warp-per-edge float4 epilogue, no shuffles):
//   Phase 1: EW[64,128] = [ea|te][64,48] @ W1_et[48,128]  (tf32 mma)
//   Phase 2: stage EW to shared Cs[64][132] (stride*4B = 528 = 16B multiple),
//   Phase 3: 16 rounds; round r: warp w handles edge e=r*4+w, lane l handles
//            cols [4l,4l+4): float4 LDS + float4 XA gather + relu +
//            one red.add.v4 per lane.
// ---------------------------------------------------------------------------
__global__ void __launch_bounds__(128) edge_mma3(
    const float* __restrict__ edge_attr, const float* __restrict__ t,
    const float* __restrict__ time_w, const float* __restrict__ time_b,
    const float* __restrict__ msg_w1, const int* __restrict__ edge_index,
    const float* __restrict__ XA, float* __restrict__ H, float* __restrict__ CNT)
{
    // Raw shared buffer: phase1 = Ae[64][53] u32 (13568B) + Bw[48][129] u32 (24768B)
    //                    phase2/3 = Cs[64][132] floats (33792B) — reused
    __shared__ __align__(16) char sm_raw[13568 + 24768];
    uint32_t (*Ae)[53]  = reinterpret_cast<uint32_t(*)[53]>(sm_raw);
    uint32_t (*Bw)[129] = reinterpret_cast<uint32_t(*)[129]>(sm_raw + 13568);
    float    (*Cs)[132] = reinterpret_cast<float(*)[132]>(sm_raw);
    __shared__ int src_s[64], tgt_s[64];
    __shared__ float tw_s[TIME_D], tb_s[TIME_D];

    const int tid = threadIdx.x;
    const int lane = tid & 31, w = tid >> 5;
    const int lr = lane >> 2, lc = lane & 3;
    const int e0 = blockIdx.x * 64;

    if (tid < TIME_D) { tw_s[tid] = time_w[tid]; tb_s[tid] = time_b[tid]; }
    if (tid >= 64) {
        int i = tid - 64;
        int tg = edge_index[N_EDGES + e0 + i];
        tgt_s[i] = tg;
        atomicAdd(&CNT[tg], 1.0f);
    } else {
        src_s[tid] = edge_index[e0 + tid];
    }
    // W1_et -> Bw  (48 rows x 128 cols)
    #pragma unroll
    for (int i = 0; i < 12; i++) {
        int idx = i * 128 + tid;          // 0..1535 float4s
        int k = idx >> 5, n4 = idx & 31;
        float4 v = *(const float4*)&msg_w1[(size_t)(NODE_F + k) * MSG_D + n4 * 4];
        Bw[k][n4*4+0] = f2tf(v.x); Bw[k][n4*4+1] = f2tf(v.y);
        Bw[k][n4*4+2] = f2tf(v.z); Bw[k][n4*4+3] = f2tf(v.w);
    }
    // edge_attr -> Ae[:, 0:32]
    #pragma unroll
    for (int i = 0; i < 4; i++) {
        int idx = i * 128 + tid;          // 0..511 float4s
        int e = idx >> 3, k4 = idx & 7;
        float4 v = *(const float4*)&edge_attr[(size_t)(e0 + e) * EDGE_F + k4 * 4];
        Ae[e][k4*4+0] = f2tf(v.x); Ae[e][k4*4+1] = f2tf(v.y);
        Ae[e][k4*4+2] = f2tf(v.z); Ae[e][k4*4+3] = f2tf(v.w);
    }
    __syncthreads();
    // time enc -> Ae[:, 32:48]
    #pragma unroll
    for (int i = 0; i < 8; i++) {
        int idx = i * 128 + tid;          // 0..1023
        int e = idx >> 4, k = idx & 15;
        Ae[e][EDGE_F + k] = f2tf(cosf(t[e0 + e] * tw_s[k] + tb_s[k]));
    }
    __syncthreads();

    // A fragments into registers (frees Ae for reuse after the next sync)
    uint32_t a[6][4];
    #pragma unroll
    for (int kk = 0; kk < 6; kk++) {
        a[kk][0] = Ae[w*16+lr  ][kk*8+lc  ];
        a[kk][1] = Ae[w*16+lr+8][kk*8+lc  ];
        a[kk][2] = Ae[w*16+lr  ][kk*8+lc+4];
        a[kk][3] = Ae[w*16+lr+8][kk*8+lc+4];
    }

    float c[16][4];
    #pragma unroll
    for (int i = 0; i < 16; i++) { c[i][0] = c[i][1] = c[i][2] = c[i][3] = 0.f; }

    #pragma unroll
    for (int kk = 0; kk < 6; kk++) {
        #pragma unroll
        for (int nt = 0; nt < 16; nt++) {
            uint32_t b0 = Bw[kk*8+lc  ][nt*8+lr];
            uint32_t b1 = Bw[kk*8+lc+4][nt*8+lr];
            mma8(c[nt], a[kk][0], a[kk][1], a[kk][2], a[kk][3], b0, b1);
        }
    }
    __syncthreads();   // all reads of Ae/Bw complete — safe to overwrite with Cs

    // Stage accumulators. Stride 132 (x4B = 528, 16B multiple): float2 stores
    // at even col offsets are 8B-aligned; float4 reads at col 4*l are 16B-aligned.
    const int er0 = w * 16 + lr, er1 = er0 + 8;
    #pragma unroll
    for (int nt = 0; nt < 16; nt++) {
        const int n = nt * 8 + lc * 2;
        *(float2*)&Cs[er0][n] = make_float2(c[nt][0], c[nt][1]);
        *(float2*)&Cs[er1][n] = make_float2(c[nt][2], c[nt][3]);
    }
    __syncthreads();

    // Epilogue: warp per edge, lane per 4 columns. No shuffles.
    // Prefetch this warp's 16 edge indices into registers first.
    int se[16], ge[16];
    #pragma unroll
    for (int r = 0; r < 16; r++) {
        se[r] = src_s[r * 4 + w];
        ge[r] = tgt_s[r * 4 + w];
    }
    #pragma unroll 4
    for (int r = 0; r < 16; r++) {
        const int e = r * 4 + w;
        float4 cv = *(const float4*)&Cs[e][lane * 4];
        float4 xv = __ldg((const float4*)&XA[(size_t)se[r] * MSG_D + lane * 4]);
        float v0 = fmaxf(cv.x + xv.x, 0.f);
        float v1 = fmaxf(cv.y + xv.y, 0.f);
        float v2 = fmaxf(cv.z + xv.z, 0.f);
        float v3 = fmaxf(cv.w + xv.w, 0.f);
        red_add_v4(&H[(size_t)ge[r] * MSG_D + lane * 4], v0, v1, v2, v3);
    }
}

// ---------------------------------------------------------------------------
__global__ void gru_kernel(const float* __restrict__ GI, const float* __restrict__ b_hh,
                           float* __restrict__ MEM)
{
    int idx = blockIdx.x * blockDim.x + threadIdx.x;
    if (idx >= N_NODES * MEM_D) return;
    int m = idx >> 7, j = idx & 127;
    const float* gi = GI + (size_t)m * (3 * MEM_D);
    float r  = sigmoidf_(gi[j]             + b_hh[j]);
    float z  = sigmoidf_(gi[MEM_D + j]     + b_hh[MEM_D + j]);
    float nn = tanhf    (gi[2 * MEM_D + j] + r * b_hh[2 * MEM_D + j]);
    MEM[idx] = (1.0f - z) * nn;
}

// ---------------------------------------------------------------------------
extern "C" void kernel_launch(void* const* d_in, const int* in_sizes, int n_in,
                              void* d_out, int out_size)
{
    const float* x         = (const float*)d_in[0];
    const float* edge_attr = (const float*)d_in[1];
    const float* t         = (const float*)d_in[2];
    const float* time_w    = (const float*)d_in[3];
    const float* time_b    = (const float*)d_in[4];
    const float* msg_w1    = (const float*)d_in[5];
    const float* msg_b1    = (const float*)d_in[6];
    const float* msg_w2    = (const float*)d_in[7];
    const float* msg_b2    = (const float*)d_in[8];
    const float* gru_w_ih  = (const float*)d_in[9];
    // d_in[10] = gru_w_hh: unused (h0 == 0)
    const float* gru_b_ih  = (const float*)d_in[11];
    const float* gru_b_hh  = (const float*)d_in[12];
    const float* out_w     = (const float*)d_in[13];
    const float* out_b     = (const float*)d_in[14];
    const int*   edge_idx  = (const int*)d_in[15];
    float* out = (float*)d_out;

    float *XA, *H, *CNT, *AGG, *GI, *MEM;
    cudaGetSymbolAddress((void**)&XA,  g_XA);
    cudaGetSymbolAddress((void**)&H,   g_H);
    cudaGetSymbolAddress((void**)&CNT, g_CNT);
    cudaGetSymbolAddress((void**)&AGG, g_AGG);
    cudaGetSymbolAddress((void**)&GI,  g_GI);
    cudaGetSymbolAddress((void**)&MEM, g_MEM);

    const int M = N_NODES;
    const int mtiles = (M + 63) / 64;   // 782

    // 1) zero H, CNT
    zero_kernel<<<(N_NODES * MSG_D + 255) / 256, 256>>>(H, CNT);

    // 2) XA = x @ W1_x + b1
    gemm_tf32<false, false><<<dim3(mtiles, 2), 128>>>(x, msg_w1, msg_b1, nullptr, XA, M, MSG_D);

    // 3) edge stage (tensor-core MLP + warp-per-edge epilogue)
    edge_mma3<<<N_EDGES / 64, 128>>>(edge_attr, t, time_w, time_b, msg_w1, edge_idx, XA, H, CNT);

    // 4) AGG = mean(H) @ W2 + b2  (masked to 0 where cnt==0)
    gemm_tf32<false, true><<<dim3(mtiles, 2), 128>>>(H, msg_w2, msg_b2, CNT, AGG, M, MEM_D);

    // 5) GI = AGG @ W_ih^T + b_ih
    gemm_tf32<true, false><<<dim3(mtiles, 6), 128>>>(AGG, gru_w_ih, gru_b_ih, nullptr, GI, M, 3 * MEM_D);

    // 6) GRU elementwise
    gru_kernel<<<(N_NODES * MEM_D + 255) / 256, 256>>>(GI, gru_b_hh, MEM);

    // 7) out = MEM @ out_w^T + out_b
    gemm_tf32<true, false><<<dim3(mtiles, 2), 128>>>(MEM, out_w, out_b, nullptr, out, M, NODE_F);
}

// round 11
// speedup vs baseline: 1.8868x; 1.0910x over previous
#include <cuda_runtime.h>
#include <math.h>
#include <stdint.h>

#define N_NODES 50000
#define N_EDGES 800000
#define NODE_F  128
#define EDGE_F  32
#define TIME_D  16
#define MEM_D   128
#define MSG_D   128

// Scratch (device globals — no allocation allowed)
__device__ float g_XA[N_NODES * MSG_D];    // x@W1_x + b1 per node
__device__ float g_H[N_NODES * MSG_D];     // sum of h1 per target node
__device__ float g_CNT[N_NODES];           // in-degree
__device__ float g_AGG[N_NODES * MEM_D];
__device__ float g_GI[N_NODES * 3 * MEM_D];
__device__ float g_MEM[N_NODES * MEM_D];

__device__ __forceinline__ uint32_t f2tf(float f) {
    uint32_t r; asm("cvt.rna.tf32.f32 %0, %1;" : "=r"(r) : "f"(f)); return r;
}

__device__ __forceinline__ void mma8(float* c, uint32_t a0, uint32_t a1, uint32_t a2,
                                     uint32_t a3, uint32_t b0, uint32_t b1) {
    asm volatile(
        "mma.sync.aligned.m16n8k8.row.col.f32.tf32.tf32.f32 "
        "{%0,%1,%2,%3}, {%4,%5,%6,%7}, {%8,%9}, {%0,%1,%2,%3};"
        : "+f"(c[0]), "+f"(c[1]), "+f"(c[2]), "+f"(c[3])
        : "r"(a0), "r"(a1), "r"(a2), "r"(a3), "r"(b0), "r"(b1));
}

__device__ __forceinline__ void red_add_v4(float* addr, float a, float b, float c, float d) {
    asm volatile("red.global.add.v4.f32 [%0], {%1,%2,%3,%4};"
                 :: "l"(addr), "f"(a), "f"(b), "f"(c), "f"(d) : "memory");
}

__device__ __forceinline__ float sigmoidf_(float x) { return 1.0f / (1.0f + expf(-x)); }

// ---------------------------------------------------------------------------
__global__ void zero_kernel(float* __restrict__ H, float* __restrict__ C) {
    int idx = blockIdx.x * blockDim.x + threadIdx.x;
    if (idx < N_NODES * MSG_D) H[idx] = 0.0f;
    if (idx < N_NODES) C[idx] = 0.0f;
}

// ---------------------------------------------------------------------------
// tf32 tensor-core GEMM: C[M,N] = A[M,128] @ B (+bias)  (proven in R6/R8/R10)
// ---------------------------------------------------------------------------
template<bool TRANSB, bool MEANMASK>
__global__ void __launch_bounds__(128) gemm_tf32(
    const float* __restrict__ A, const float* __restrict__ B,
    const float* __restrict__ bias, const float* __restrict__ cnt,
    float* __restrict__ C, int M, int N)
{
    __shared__ uint32_t As[64][68];
    __shared__ uint32_t Bs[64][73];
    const int tid = threadIdx.x;
    const int lane = tid & 31, w = tid >> 5;
    const int lr = lane >> 2, lc = lane & 3;
    const int m0 = blockIdx.x * 64, n0 = blockIdx.y * 64;

    float c[8][4];
    #pragma unroll
    for (int i = 0; i < 8; i++) { c[i][0] = c[i][1] = c[i][2] = c[i][3] = 0.f; }

    for (int ks = 0; ks < 128; ks += 64) {
        #pragma unroll
        for (int i = 0; i < 8; i++) {
            int idx = i * 128 + tid;
            int m = idx >> 4, k4 = idx & 15;
            int gm = m0 + m;
            float4 v = make_float4(0.f, 0.f, 0.f, 0.f);
            if (gm < M) v = *(const float4*)&A[(size_t)gm * 128 + ks + k4 * 4];
            As[m][k4*4+0] = f2tf(v.x); As[m][k4*4+1] = f2tf(v.y);
            As[m][k4*4+2] = f2tf(v.z); As[m][k4*4+3] = f2tf(v.w);
        }
        #pragma unroll
        for (int i = 0; i < 8; i++) {
            int idx = i * 128 + tid;
            if (TRANSB) {
                int n = idx >> 4, k4 = idx & 15;
                float4 v = *(const float4*)&B[(size_t)(n0 + n) * 128 + ks + k4 * 4];
                Bs[k4*4+0][n] = f2tf(v.x); Bs[k4*4+1][n] = f2tf(v.y);
                Bs[k4*4+2][n] = f2tf(v.z); Bs[k4*4+3][n] = f2tf(v.w);
            } else {
                int k = idx >> 4, n4 = idx & 15;
                float4 v = *(const float4*)&B[(size_t)(ks + k) * N + n0 + n4 * 4];
                Bs[k][n4*4+0] = f2tf(v.x); Bs[k][n4*4+1] = f2tf(v.y);
                Bs[k][n4*4+2] = f2tf(v.z); Bs[k][n4*4+3] = f2tf(v.w);
            }
        }
        __syncthreads();
        #pragma unroll
        for (int kk = 0; kk < 8; kk++) {
            uint32_t a0 = As[w*16+lr  ][kk*8+lc  ];
            uint32_t a1 = As[w*16+lr+8][kk*8+lc  ];
            uint32_t a2 = As[w*16+lr  ][kk*8+lc+4];
            uint32_t a3 = As[w*16+lr+8][kk*8+lc+4];
            #pragma unroll
            for (int nt = 0; nt < 8; nt++) {
                uint32_t b0 = Bs[kk*8+lc  ][nt*8+lr];
                uint32_t b1 = Bs[kk*8+lc+4][nt*8+lr];
                mma8(c[nt], a0, a1, a2, a3, b0, b1);
            }
        }
        __syncthreads();
    }

    const int gm0 = m0 + w * 16 + lr, gm1 = gm0 + 8;
    float s0 = 1.f, s1 = 1.f; bool z0 = false, z1 = false;
    if (MEANMASK) {
        if (gm0 < M) { float cc = cnt[gm0]; if (cc > 0.f) s0 = 1.f / cc; else z0 = true; }
        if (gm1 < M) { float cc = cnt[gm1]; if (cc > 0.f) s1 = 1.f / cc; else z1 = true; }
    }
    #pragma unroll
    for (int nt = 0; nt < 8; nt++) {
        int n = n0 + nt * 8 + lc * 2;
        float bx = bias[n], by = bias[n + 1];
        if (gm0 < M) {
            float2 o;
            if (MEANMASK) {
                if (z0) { o.x = 0.f; o.y = 0.f; }
                else    { o.x = c[nt][0] * s0 + bx; o.y = c[nt][1] * s0 + by; }
            } else      { o.x = c[nt][0] + bx;      o.y = c[nt][1] + by; }
            *(float2*)&C[(size_t)gm0 * N + n] = o;
        }
        if (gm1 < M) {
            float2 o;
            if (MEANMASK) {
                if (z1) { o.x = 0.f; o.y = 0.f; }
                else    { o.x = c[nt][2] * s1 + bx; o.y = c[nt][3] * s1 + by; }
            } else      { o.x = c[nt][2] + bx;      o.y = c[nt][3] + by; }
            *(float2*)&C[(size_t)gm1 * N + n] = o;
        }
    }
}

// ---------------------------------------------------------------------------
// Edge kernel v4: persistent weights + grid-stride over 64-edge tiles.
//   Bw (W1_et, 24.8KB) loaded ONCE per block. Per tile: stage feats, tf32 mma,
//   two-pass Cs32 staging (32 edges each), warp-per-edge float4 epilogue.
// ---------------------------------------------------------------------------
#define EDGE_TILES   (N_EDGES / 64)     // 12500
#define EDGE_BLOCKS  2048

__global__ void __launch_bounds__(128) edge_mma4(
    const float* __restrict__ edge_attr, const float* __restrict__ t,
    const float* __restrict__ time_w, const float* __restrict__ time_b,
    const float* __restrict__ msg_w1, const int* __restrict__ edge_index,
    const float* __restrict__ XA, float* __restrict__ H, float* __restrict__ CNT)
{
    // Persistent: Bw[48][129] u32 at offset 0 (24768B)
    // Per-tile (reused): Ae[64][53] u32 (13568B)  OR  Cs[32][136] float (17408B)
    __shared__ __align__(16) char sm_raw[24768 + 17408];
    uint32_t (*Bw)[129] = reinterpret_cast<uint32_t(*)[129]>(sm_raw);
    uint32_t (*Ae)[53]  = reinterpret_cast<uint32_t(*)[53]>(sm_raw + 24768);
    float    (*Cs)[136] = reinterpret_cast<float(*)[136]>(sm_raw + 24768);
    __shared__ int src_s[64], tgt_s[64];
    __shared__ float tw_s[TIME_D], tb_s[TIME_D];

    const int tid = threadIdx.x;
    const int lane = tid & 31, w = tid >> 5;
    const int lr = lane >> 2, lc = lane & 3;

    if (tid < TIME_D) { tw_s[tid] = time_w[tid]; tb_s[tid] = time_b[tid]; }
    // W1_et -> Bw (once per block)
    #pragma unroll
    for (int i = 0; i < 12; i++) {
        int idx = i * 128 + tid;          // 0..1535 float4s
        int k = idx >> 5, n4 = idx & 31;
        float4 v = *(const float4*)&msg_w1[(size_t)(NODE_F + k) * MSG_D + n4 * 4];
        Bw[k][n4*4+0] = f2tf(v.x); Bw[k][n4*4+1] = f2tf(v.y);
        Bw[k][n4*4+2] = f2tf(v.z); Bw[k][n4*4+3] = f2tf(v.w);
    }

    for (int g = blockIdx.x; g < EDGE_TILES; g += EDGE_BLOCKS) {
        const int e0 = g * 64;
        __syncthreads();   // prev tile's epilogue reads of src/tgt/Cs done; Bw ready on 1st iter

        // indices + degree count
        if (tid >= 64) {
            int i = tid - 64;
            int tg = edge_index[N_EDGES + e0 + i];
            tgt_s[i] = tg;
            atomicAdd(&CNT[tg], 1.0f);
        } else {
            src_s[tid] = edge_index[e0 + tid];
        }
        // edge_attr -> Ae[:, 0:32]
        #pragma unroll
        for (int i = 0; i < 4; i++) {
            int idx = i * 128 + tid;      // 0..511 float4s
            int e = idx >> 3, k4 = idx & 7;
            float4 v = *(const float4*)&edge_attr[(size_t)(e0 + e) * EDGE_F + k4 * 4];
            Ae[e][k4*4+0] = f2tf(v.x); Ae[e][k4*4+1] = f2tf(v.y);
            Ae[e][k4*4+2] = f2tf(v.z); Ae[e][k4*4+3] = f2tf(v.w);
        }
        // time enc -> Ae[:, 32:48]
        #pragma unroll
        for (int i = 0; i < 8; i++) {
            int idx = i * 128 + tid;      // 0..1023
            int e = idx >> 4, k = idx & 15;
            Ae[e][EDGE_F + k] = f2tf(cosf(t[e0 + e] * tw_s[k] + tb_s[k]));
        }
        __syncthreads();

        // A fragments into registers
        uint32_t a[6][4];
        #pragma unroll
        for (int kk = 0; kk < 6; kk++) {
            a[kk][0] = Ae[w*16+lr  ][kk*8+lc  ];
            a[kk][1] = Ae[w*16+lr+8][kk*8+lc  ];
            a[kk][2] = Ae[w*16+lr  ][kk*8+lc+4];
            a[kk][3] = Ae[w*16+lr+8][kk*8+lc+4];
        }

        float c[16][4];
        #pragma unroll
        for (int i = 0; i < 16; i++) { c[i][0] = c[i][1] = c[i][2] = c[i][3] = 0.f; }

        #pragma unroll
        for (int kk = 0; kk < 6; kk++) {
            #pragma unroll
            for (int nt = 0; nt < 16; nt++) {
                uint32_t b0 = Bw[kk*8+lc  ][nt*8+lr];
                uint32_t b1 = Bw[kk*8+lc+4][nt*8+lr];
                mma8(c[nt], a[kk][0], a[kk][1], a[kk][2], a[kk][3], b0, b1);
            }
        }
        __syncthreads();   // Ae reads done — safe to overwrite with Cs

        // -------- pass 0: edges 0..31 (rows held by warps 0,1) --------
        if (w < 2) {
            const int er0 = w * 16 + lr, er1 = er0 + 8;     // 0..31
            #pragma unroll
            for (int nt = 0; nt < 16; nt++) {
                const int n = nt * 8 + lc * 2;
                *(float2*)&Cs[er0][n] = make_float2(c[nt][0], c[nt][1]);
                *(float2*)&Cs[er1][n] = make_float2(c[nt][2], c[nt][3]);
            }
        }
        __syncthreads();
        #pragma unroll 4
        for (int r = 0; r < 8; r++) {
            const int e = r * 4 + w;                        // 0..31
            const int s = src_s[e], gt = tgt_s[e];
            float4 cv = *(const float4*)&Cs[e][lane * 4];
            float4 xv = __ldg((const float4*)&XA[(size_t)s * MSG_D + lane * 4]);
            red_add_v4(&H[(size_t)gt * MSG_D + lane * 4],
                       fmaxf(cv.x + xv.x, 0.f), fmaxf(cv.y + xv.y, 0.f),
                       fmaxf(cv.z + xv.z, 0.f), fmaxf(cv.w + xv.w, 0.f));
        }
        __syncthreads();

        // -------- pass 1: edges 32..63 (rows held by warps 2,3) --------
        if (w >= 2) {
            const int er0 = w * 16 + lr - 32, er1 = er0 + 8; // 0..31
            #pragma unroll
            for (int nt = 0; nt < 16; nt++) {
                const int n = nt * 8 + lc * 2;
                *(float2*)&Cs[er0][n] = make_float2(c[nt][0], c[nt][1]);
                *(float2*)&Cs[er1][n] = make_float2(c[nt][2], c[nt][3]);
            }
        }
        __syncthreads();
        #pragma unroll 4
        for (int r = 0; r < 8; r++) {
            const int e = 32 + r * 4 + w;                   // 32..63
            const int s = src_s[e], gt = tgt_s[e];
            float4 cv = *(const float4*)&Cs[e - 32][lane * 4];
            float4 xv = __ldg((const float4*)&XA[(size_t)s * MSG_D + lane * 4]);
            red_add_v4(&H[(size_t)gt * MSG_D + lane * 4],
                       fmaxf(cv.x + xv.x, 0.f), fmaxf(cv.y + xv.y, 0.f),
                       fmaxf(cv.z + xv.z, 0.f), fmaxf(cv.w + xv.w, 0.f));
        }
    }
}

// ---------------------------------------------------------------------------
__global__ void gru_kernel(const float* __restrict__ GI, const float* __restrict__ b_hh,
                           float* __restrict__ MEM)
{
    int idx = blockIdx.x * blockDim.x + threadIdx.x;
    if (idx >= N_NODES * MEM_D) return;
    int m = idx >> 7, j = idx & 127;
    const float* gi = GI + (size_t)m * (3 * MEM_D);
    float r  = sigmoidf_(gi[j]             + b_hh[j]);
    float z  = sigmoidf_(gi[MEM_D + j]     + b_hh[MEM_D + j]);
    float nn = tanhf    (gi[2 * MEM_D + j] + r * b_hh[2 * MEM_D + j]);
    MEM[idx] = (1.0f - z) * nn;
}

// ---------------------------------------------------------------------------
extern "C" void kernel_launch(void* const* d_in, const int* in_sizes, int n_in,
                              void* d_out, int out_size)
{
    const float* x         = (const float*)d_in[0];
    const float* edge_attr = (const float*)d_in[1];
    const float* t         = (const float*)d_in[2];
    const float* time_w    = (const float*)d_in[3];
    const float* time_b    = (const float*)d_in[4];
    const float* msg_w1    = (const float*)d_in[5];
    const float* msg_b1    = (const float*)d_in[6];
    const float* msg_w2    = (const float*)d_in[7];
    const float* msg_b2    = (const float*)d_in[8];
    const float* gru_w_ih  = (const float*)d_in[9];
    // d_in[10] = gru_w_hh: unused (h0 == 0)
    const float* gru_b_ih  = (const float*)d_in[11];
    const float* gru_b_hh  = (const float*)d_in[12];
    const float* out_w     = (const float*)d_in[13];
    const float* out_b     = (const float*)d_in[14];
    const int*   edge_idx  = (const int*)d_in[15];
    float* out = (float*)d_out;

    float *XA, *H, *CNT, *AGG, *GI, *MEM;
    cudaGetSymbolAddress((void**)&XA,  g_XA);
    cudaGetSymbolAddress((void**)&H,   g_H);
    cudaGetSymbolAddress((void**)&CNT, g_CNT);
    cudaGetSymbolAddress((void**)&AGG, g_AGG);
    cudaGetSymbolAddress((void**)&GI,  g_GI);
    cudaGetSymbolAddress((void**)&MEM, g_MEM);

    const int M = N_NODES;
    const int mtiles = (M + 63) / 64;   // 782

    // 1) zero H, CNT
    zero_kernel<<<(N_NODES * MSG_D + 255) / 256, 256>>>(H, CNT);

    // 2) XA = x @ W1_x + b1
    gemm_tf32<false, false><<<dim3(mtiles, 2), 128>>>(x, msg_w1, msg_b1, nullptr, XA, M, MSG_D);

    // 3) edge stage (persistent-weight tensor-core MLP + scatter)
    edge_mma4<<<EDGE_BLOCKS, 128>>>(edge_attr, t, time_w, time_b, msg_w1, edge_idx, XA, H, CNT);

    // 4) AGG = mean(H) @ W2 + b2  (masked to 0 where cnt==0)
    gemm_tf32<false, true><<<dim3(mtiles, 2), 128>>>(H, msg_w2, msg_b2, CNT, AGG, M, MEM_D);

    // 5) GI = AGG @ W_ih^T + b_ih
    gemm_tf32<true, false><<<dim3(mtiles, 6), 128>>>(AGG, gru_w_ih, gru_b_ih, nullptr, GI, M, 3 * MEM_D);

    // 6) GRU elementwise
    gru_kernel<<<(N_NODES * MEM_D + 255) / 256, 256>>>(GI, gru_b_hh, MEM);

    // 7) out = MEM @ out_w^T + out_b
    gemm_tf32<true, false><<<dim3(mtiles, 2), 128>>>(MEM, out_w, out_b, nullptr, out, M, NODE_F);
}